// round 6
// baseline (speedup 1.0000x reference)
#include <cuda_runtime.h>
#include <math.h>

// Problem constants (fixed by reference)
#define BATCH   2
#define NFACES  4096
#define IS      256
#define NPIX    (IS*IS)
#define TPD     8               // tiles per dimension (32x32-pixel tiles)
#define NTILES  (TPD*TPD)       // 64 tiles per batch image
#define RECSZ   24              // floats per precomputed face record (6 x float4)
#define FARV    100.0f
#define NEARV   0.1f
#define PSTEP   (2.0f/256.0f)   // xp/yp delta for one pixel

// Scratch (static device globals — no dynamic allocation allowed).
//   q0 = {e0x, e0y, e0c, z0}   edge 0->1 coeffs (edge = ex*xp + ey*yp + ec)
//   q1 = {e1x, e1y, e1c, z1}
//   q2 = {e2x, e2y, e2c, z2}
//   q3 = {i00, i01, i02, 1/z0} barycentric inverse row 0 (already / det)
//   q4 = {i10, i11, i12, 1/z1}
//   q5 = {i20, i21, i22, 1/z2}
__device__ float g_rec[BATCH*NFACES*RECSZ];
__device__ int   g_cnt[BATCH*NTILES];        // zero-init; render restores zeros each run
__device__ int   g_list[BATCH*NTILES*NFACES];

// One thread per (batch, face): precompute record + bin into overlapped tiles.
__global__ void bin_kernel(const float* __restrict__ faces) {
    int gid = blockIdx.x*blockDim.x + threadIdx.x;
    if (gid >= BATCH*NFACES) return;
    int b = gid / NFACES;
    int f = gid - b*NFACES;

    const float* fp = faces + (size_t)gid*9;
    float x0=fp[0], y0=fp[1], z0=fp[2];
    float x1=fp[3], y1=fp[4], z1=fp[5];
    float x2=fp[6], y2=fp[7], z2=fp[8];

    float det  = x2*(y0-y1) + x0*(y1-y2) + x1*(y2-y0);
    float detc = (det >= 0.f) ? fmaxf(det, 1e-10f) : fminf(det, -1e-10f);

    float* r = g_rec + (size_t)gid*RECSZ;
    { float dX=x1-x0, dY=y1-y0; r[0]=-dY; r[1]=dX; r[2]=x0*dY - y0*dX; r[3]=z0; }
    { float dX=x2-x1, dY=y2-y1; r[4]=-dY; r[5]=dX; r[6]=x1*dY - y1*dX; r[7]=z1; }
    { float dX=x0-x2, dY=y0-y2; r[8]=-dY; r[9]=dX; r[10]=x2*dY - y2*dX; r[11]=z2; }
    r[12]=(y1-y2)/detc; r[13]=(x2-x1)/detc; r[14]=(x1*y2-x2*y1)/detc; r[15]=1.0f/z0;
    r[16]=(y2-y0)/detc; r[17]=(x0-x2)/detc; r[18]=(x2*y0-x0*y2)/detc; r[19]=1.0f/z1;
    r[20]=(y0-y1)/detc; r[21]=(x1-x0)/detc; r[22]=(x0*y1-x1*y0)/detc; r[23]=1.0f/z2;

    // Winding cull: e0+e1+e2 == det identically, so all-edges>=0 is impossible
    // when det < 0.
    if (det <= 0.f) return;

    // Conservative pixel bbox. xp(ix) = (2*ix+1-256)/256, yp(row) = (255-2*row)/256.
    float xmn = fminf(x0, fminf(x1,x2)), xmx = fmaxf(x0, fmaxf(x1,x2));
    float ymn = fminf(y0, fminf(y1,y2)), ymx = fmaxf(y0, fmaxf(y1,y2));
    int ix0 = (int)floorf((256.f*xmn + 255.f)*0.5f) - 1;
    int ix1 = (int)ceilf ((256.f*xmx + 255.f)*0.5f) + 1;
    int iy0 = (int)floorf((255.f - 256.f*ymx)*0.5f) - 1;
    int iy1 = (int)ceilf ((255.f - 256.f*ymn)*0.5f) + 1;
    if (ix1 < 0 || ix0 > IS-1 || iy1 < 0 || iy0 > IS-1) return;
    ix0 = max(ix0, 0); ix1 = min(ix1, IS-1);
    iy0 = max(iy0, 0); iy1 = min(iy1, IS-1);

    int tx0 = ix0 >> 5, tx1 = ix1 >> 5;      // 32-pixel tiles
    int ty0 = iy0 >> 5, ty1 = iy1 >> 5;
    for (int ty = ty0; ty <= ty1; ty++)
        for (int tx = tx0; tx <= tx1; tx++) {
            int t = b*NTILES + ty*TPD + tx;
            int pos = atomicAdd(&g_cnt[t], 1);
            if (pos < NFACES)
                g_list[(size_t)t*NFACES + pos] = f;
        }
}

// One block per (tile, batch). 256 threads; each thread owns a 2x2 pixel quad
// of the 32x32 tile. Loop state per pixel: (bestZ, bestF) only — the winner's
// barycentric weights are recomputed in the epilogue from its record.
__global__ void __launch_bounds__(256) render_kernel(
        const float* __restrict__ tex, float* __restrict__ out) {
    int tile = blockIdx.x;
    int b    = blockIdx.y;
    int tx = tile & (TPD-1), ty = tile >> 3;
    int qx = threadIdx.x & 15, qy = threadIdx.x >> 4;
    int px0 = (tx<<5) + (qx<<1), py0 = (ty<<5) + (qy<<1);

    float xp0 =  (2.f*(float)px0 + 1.f - (float)IS) * (1.f/(float)IS);
    float yp0 = -(2.f*(float)py0 + 1.f - (float)IS) * (1.f/(float)IS);

    int cidx = b*NTILES + tile;
    int cnt  = min(g_cnt[cidx], NFACES);
    __syncthreads();                       // all reads of g_cnt before the reset
    if (threadIdx.x == 0) g_cnt[cidx] = 0; // self-reset: next run starts clean
    const int* list = g_list + (size_t)cidx*NFACES;
    const float* recb = g_rec + (size_t)b*NFACES*RECSZ;

    float bz00=FARV, bz10=FARV, bz01=FARV, bz11=FARV;
    int   bf00=-1,   bf10=-1,   bf01=-1,   bf11=-1;

    // Software-pipelined: prefetch next face's index + edge rows (MLP=2).
    int f = 0; float4 n0, n1, n2;
    if (cnt > 0) {
        f = __ldg(list);
        const float4* R = (const float4*)(recb + (size_t)f*RECSZ);
        n0 = __ldg(R+0); n1 = __ldg(R+1); n2 = __ldg(R+2);
    }
    for (int i = 0; i < cnt; i++) {
        int fc = f;
        float4 p0 = n0, p1 = n1, p2 = n2;
        if (i+1 < cnt) {
            f = __ldg(list + i + 1);
            const float4* R = (const float4*)(recb + (size_t)f*RECSZ);
            n0 = __ldg(R+0); n1 = __ldg(R+1); n2 = __ldg(R+2);
        }
        // Edge values at the quad's 4 pixels via incremental stepping.
        float e0 = fmaf(p0.x, xp0, fmaf(p0.y, yp0, p0.z));
        float e1 = fmaf(p1.x, xp0, fmaf(p1.y, yp0, p1.z));
        float e2 = fmaf(p2.x, xp0, fmaf(p2.y, yp0, p2.z));
        float dx0 = p0.x*PSTEP, dy0 = p0.y*PSTEP;
        float dx1 = p1.x*PSTEP, dy1 = p1.y*PSTEP;
        float dx2 = p2.x*PSTEP, dy2 = p2.y*PSTEP;
        bool in00 =  e0       >=0.f &&  e1       >=0.f &&  e2       >=0.f;
        bool in10 = (e0+dx0)  >=0.f && (e1+dx1)  >=0.f && (e2+dx2)  >=0.f;
        bool in01 = (e0-dy0)  >=0.f && (e1-dy1)  >=0.f && (e2-dy2)  >=0.f;
        bool in11 = (e0+dx0-dy0)>=0.f && (e1+dx1-dy1)>=0.f && (e2+dx2-dy2)>=0.f;
        if (!(in00 | in10 | in01 | in11)) continue;

        const float4* Rb = (const float4*)(recb + (size_t)fc*RECSZ);
        float4 q3 = __ldg(Rb+3), q4 = __ldg(Rb+4), q5 = __ldg(Rb+5);

        auto depth = [&](bool in, float xp, float yp, float& bZ, int& bF) {
            if (!in) return;
            float w0 = __saturatef(fmaf(q3.x, xp, fmaf(q3.y, yp, q3.z)));
            float w1 = __saturatef(fmaf(q4.x, xp, fmaf(q4.y, yp, q4.z)));
            float w2 = __saturatef(fmaf(q5.x, xp, fmaf(q5.y, yp, q5.z)));
            float ws = fmaxf(w0 + w1 + w2, 1e-10f);
            // zp = ws / sum(w * 1/z)  (== reference's normalized form)
            float s  = fmaf(w0, q3.w, fmaf(w1, q4.w, w2*q5.w));
            float zp = __fdividef(ws, s);       // s<=0 -> inf -> fails range test
            if (zp > NEARV && zp < FARV) {
                if (zp < bZ || (zp == bZ && (unsigned)fc < (unsigned)bF)) {
                    bZ = zp; bF = fc;
                }
            }
        };
        depth(in00, xp0,       yp0,       bz00, bf00);
        depth(in10, xp0+PSTEP, yp0,       bz10, bf10);
        depth(in01, xp0,       yp0-PSTEP, bz01, bf01);
        depth(in11, xp0+PSTEP, yp0-PSTEP, bz11, bf11);
    }

    // Epilogue: recompute the winner's weights, trilinear sample (T=4), write.
    auto shade = [&](int px, int py, float bZ, int bF) {
        float cr = 0.f, cg = 0.f, cb = 0.f, alpha = 0.f;
        if (bF >= 0) {
            alpha = 1.f;
            float xp =  (2.f*(float)px + 1.f - (float)IS) * (1.f/(float)IS);
            float yp = -(2.f*(float)py + 1.f - (float)IS) * (1.f/(float)IS);
            const float4* R = (const float4*)(recb + (size_t)bF*RECSZ);
            float4 q3 = __ldg(R+3), q4 = __ldg(R+4), q5 = __ldg(R+5);
            float w0 = __saturatef(fmaf(q3.x, xp, fmaf(q3.y, yp, q3.z)));
            float w1 = __saturatef(fmaf(q4.x, xp, fmaf(q4.y, yp, q4.z)));
            float w2 = __saturatef(fmaf(q5.x, xp, fmaf(q5.y, yp, q5.z)));
            float ws = fmaxf(w0 + w1 + w2, 1e-10f);
            float inws = __fdividef(1.f, ws);
            float zt = 3.f * bZ;                                   // (T-1) * zp
            float t0 = fminf(fmaxf(w0*inws * zt * q3.w, 0.f), 2.999f);
            float t1 = fminf(fmaxf(w1*inws * zt * q4.w, 0.f), 2.999f);
            float t2 = fminf(fmaxf(w2*inws * zt * q5.w, 0.f), 2.999f);
            int i0 = (int)t0, i1 = (int)t1, i2 = (int)t2;
            float f0 = t0-(float)i0, f1 = t1-(float)i1, f2 = t2-(float)i2;
            float a0 = 1.f-f0, a1 = 1.f-f1, a2 = 1.f-f2;
            const float* tb = tex + (size_t)(b*NFACES + bF)*192;   // 4*4*4*3
            #pragma unroll
            for (int pn = 0; pn < 8; pn++) {
                int c0 = pn & 1, c1 = (pn>>1) & 1, c2 = (pn>>2) & 1;
                float wc = (c0 ? f0 : a0) * (c1 ? f1 : a1) * (c2 ? f2 : a2);
                int lin = ((i0+c0)*4 + (i1+c1))*4 + (i2+c2);
                const float* tp = tb + lin*3;
                cr = fmaf(wc, __ldg(tp+0), cr);
                cg = fmaf(wc, __ldg(tp+1), cg);
                cb = fmaf(wc, __ldg(tp+2), cb);
            }
        }
        size_t p = (size_t)b*NPIX + (size_t)py*IS + px;
        out[p*3 + 0] = cr;
        out[p*3 + 1] = cg;
        out[p*3 + 2] = cb;
        out[(size_t)BATCH*NPIX*3 + p] = alpha;
        out[(size_t)BATCH*NPIX*4 + p] = bZ;
    };
    shade(px0,   py0,   bz00, bf00);
    shade(px0+1, py0,   bz10, bf10);
    shade(px0,   py0+1, bz01, bf01);
    shade(px0+1, py0+1, bz11, bf11);
}

extern "C" void kernel_launch(void* const* d_in, const int* in_sizes, int n_in,
                              void* d_out, int out_size) {
    const float* faces = (const float*)d_in[0];     // (2, 4096, 3, 3) f32
    const float* tex   = (const float*)d_in[1];     // (2, 4096, 4, 4, 4, 3) f32
    float* out = (float*)d_out;                     // 655360 f32: rgb | alpha | zp

    bin_kernel<<<(BATCH*NFACES + 127)/128, 128>>>(faces);
    render_kernel<<<dim3(NTILES, BATCH), 256>>>(tex, out);
}